// round 8
// baseline (speedup 1.0000x reference)
#include <cuda_runtime.h>
#include <math.h>
#include <stdint.h>

#define S_LEN    2048
#define DIM      3072
#define HEADS    24
#define HEAD_DIM 128

// Scratch (no cudaMalloc allowed): q, k, v post-projection
__device__ float g_q[S_LEN * DIM];
__device__ float g_k[S_LEN * DIM];
__device__ float g_v[S_LEN * DIM];

// ---- helpers -------------------------------------------------------------
__device__ __forceinline__ uint32_t tf32_rna(float x) {
    uint32_t r;
    asm("cvt.rna.tf32.f32 %0, %1;" : "=r"(r) : "f"(x));
    return r;
}
__device__ __forceinline__ void mma_tf32(float c[4], const uint32_t a[4], const uint32_t b[2]) {
    asm volatile(
        "mma.sync.aligned.m16n8k8.row.col.f32.tf32.tf32.f32 "
        "{%0,%1,%2,%3}, {%4,%5,%6,%7}, {%8,%9}, {%0,%1,%2,%3};"
        : "+f"(c[0]), "+f"(c[1]), "+f"(c[2]), "+f"(c[3])
        : "r"(a[0]), "r"(a[1]), "r"(a[2]), "r"(a[3]), "r"(b[0]), "r"(b[1]));
}

// ===========================================================================
// Stage 1: QKV projection via mma.sync tf32 (A and B plain tf32-rna).
// CTA tile 128x128, K-chunk 32, double-buffered smem, 8 warps (2m x 4n),
// warp tile 64x32. Smem halved vs round 7 (no A-lo) -> 2 CTAs/SM.
// ===========================================================================
#define QA_STRIDE 36
#define QB_STRIDE 136
#define QA_FLOATS (128 * QA_STRIDE)
#define QB_FLOATS (32 * QB_STRIDE)
#define QBUF_FLOATS (QA_FLOATS + QB_FLOATS)      // 8960
#define QSMEM_BYTES (2 * QBUF_FLOATS * 4)        // 71680
#define NCHUNK (DIM / 32)

__global__ __launch_bounds__(256, 2) void qkv_mma_kernel(
    const float* __restrict__ x,
    const float* __restrict__ Wq, const float* __restrict__ bq,
    const float* __restrict__ Wk, const float* __restrict__ bk,
    const float* __restrict__ Wv, const float* __restrict__ bv)
{
    extern __shared__ float smem[];
    const float* W; const float* bias; float* out;
    if (blockIdx.z == 0)      { W = Wq; bias = bq; out = g_q; }
    else if (blockIdx.z == 1) { W = Wk; bias = bk; out = g_k; }
    else                      { W = Wv; bias = bv; out = g_v; }

    const int tid  = threadIdx.x;
    const int wid  = tid >> 5;
    const int lane = tid & 31;
    const int g    = lane >> 2;
    const int tg   = lane & 3;
    const int wm   = wid >> 2;
    const int wn   = wid & 3;
    const int row0 = blockIdx.y * 128;
    const int col0 = blockIdx.x * 128;

    const int arow = tid >> 1;
    const int acol = (tid & 1) * 16;
    const int brow = tid >> 3;
    const int bcol = (tid & 7) * 16;

    const float* xA = x + (size_t)(row0 + arow) * DIM + acol;
    const float* wB = W + (size_t)brow * DIM + col0 + bcol;

    float acc[4][4][4];
    #pragma unroll
    for (int i = 0; i < 4; i++)
        #pragma unroll
        for (int j = 0; j < 4; j++)
            #pragma unroll
            for (int r = 0; r < 4; r++) acc[i][j][r] = 0.f;

    auto As = [&](int b) { return smem + (size_t)b * QBUF_FLOATS; };
    auto Bs = [&](int b) { return smem + (size_t)b * QBUF_FLOATS + QA_FLOATS; };

    {
        #pragma unroll
        for (int j = 0; j < 4; j++) {
            float4 v = *(const float4*)(xA + j * 4);
            uint4 h;
            h.x = tf32_rna(v.x); h.y = tf32_rna(v.y);
            h.z = tf32_rna(v.z); h.w = tf32_rna(v.w);
            *(uint4*)(As(0) + arow * QA_STRIDE + acol + j * 4) = h;
        }
        #pragma unroll
        for (int j = 0; j < 4; j++) {
            float4 v = *(const float4*)(wB + j * 4);
            uint4 h;
            h.x = tf32_rna(v.x); h.y = tf32_rna(v.y);
            h.z = tf32_rna(v.z); h.w = tf32_rna(v.w);
            *(uint4*)(Bs(0) + brow * QB_STRIDE + bcol + j * 4) = h;
        }
    }

    for (int c = 0; c < NCHUNK; c++) {
        __syncthreads();
        const int b = c & 1;
        const bool has_next = (c + 1) < NCHUNK;

        float4 av[4], bv[4];
        if (has_next) {
            const int kn = (c + 1) * 32;
            #pragma unroll
            for (int j = 0; j < 4; j++) av[j] = *(const float4*)(xA + kn + j * 4);
            #pragma unroll
            for (int j = 0; j < 4; j++) bv[j] = *(const float4*)(wB + (size_t)kn * DIM + j * 4);
        }

        const uint32_t* Ah = (const uint32_t*)As(b);
        const uint32_t* Bp = (const uint32_t*)Bs(b);
        #pragma unroll
        for (int kk8 = 0; kk8 < 4; kk8++) {
            const int kk = kk8 * 8;
            uint32_t ah[4][4], bb[4][2];
            #pragma unroll
            for (int i = 0; i < 4; i++) {
                const int r = wm * 64 + i * 16 + g;
                ah[i][0] = Ah[(r)     * QA_STRIDE + kk + tg];
                ah[i][1] = Ah[(r + 8) * QA_STRIDE + kk + tg];
                ah[i][2] = Ah[(r)     * QA_STRIDE + kk + tg + 4];
                ah[i][3] = Ah[(r + 8) * QA_STRIDE + kk + tg + 4];
            }
            #pragma unroll
            for (int j = 0; j < 4; j++) {
                const int n = wn * 32 + j * 8 + g;
                bb[j][0] = Bp[(kk + tg)     * QB_STRIDE + n];
                bb[j][1] = Bp[(kk + tg + 4) * QB_STRIDE + n];
            }
            #pragma unroll
            for (int i = 0; i < 4; i++)
                #pragma unroll
                for (int j = 0; j < 4; j++)
                    mma_tf32(acc[i][j], ah[i], bb[j]);
        }

        if (has_next) {
            const int nb = b ^ 1;
            #pragma unroll
            for (int j = 0; j < 4; j++) {
                uint4 h;
                h.x = tf32_rna(av[j].x); h.y = tf32_rna(av[j].y);
                h.z = tf32_rna(av[j].z); h.w = tf32_rna(av[j].w);
                *(uint4*)(As(nb) + arow * QA_STRIDE + acol + j * 4) = h;
            }
            #pragma unroll
            for (int j = 0; j < 4; j++) {
                uint4 h;
                h.x = tf32_rna(bv[j].x); h.y = tf32_rna(bv[j].y);
                h.z = tf32_rna(bv[j].z); h.w = tf32_rna(bv[j].w);
                *(uint4*)(Bs(nb) + brow * QB_STRIDE + bcol + j * 4) = h;
            }
        }
    }

    #pragma unroll
    for (int j = 0; j < 4; j++) {
        const int n = col0 + wn * 32 + j * 8 + 2 * tg;
        const float2 bb = *(const float2*)(bias + n);
        #pragma unroll
        for (int i = 0; i < 4; i++) {
            const int r = row0 + wm * 64 + i * 16 + g;
            float2 o0 = make_float2(acc[i][j][0] + bb.x, acc[i][j][1] + bb.y);
            float2 o1 = make_float2(acc[i][j][2] + bb.x, acc[i][j][3] + bb.y);
            *(float2*)(out + (size_t)r * DIM + n)       = o0;
            *(float2*)(out + (size_t)(r + 8) * DIM + n) = o1;
        }
    }
}

// ---------------------------------------------------------------------------
// Stage 2: per-head RMSNorm + RoPE applied in place to g_q and g_k.
// ---------------------------------------------------------------------------
__global__ __launch_bounds__(256) void rms_rope_kernel(
    const float* __restrict__ cosb, const float* __restrict__ sinb,
    const float* __restrict__ gq, const float* __restrict__ gk)
{
    const int gw   = (blockIdx.x * blockDim.x + threadIdx.x) >> 5;
    const int lane = threadIdx.x & 31;
    const int rows = S_LEN * HEADS;
    if (gw >= 2 * rows) return;

    const int t  = (gw >= rows) ? 1 : 0;
    const int rr = t ? (gw - rows) : gw;
    const int s  = rr / HEADS;

    float* ptr = (t ? g_k : g_q) + (size_t)rr * HEAD_DIM;
    const float* g = t ? gk : gq;

    float4 vx = *(float4*)(ptr + lane * 4);
    float ss = vx.x * vx.x + vx.y * vx.y + vx.z * vx.z + vx.w * vx.w;
    #pragma unroll
    for (int o = 16; o > 0; o >>= 1) ss += __shfl_xor_sync(0xffffffffu, ss, o);
    const float rnorm = rsqrtf(ss * (1.0f / HEAD_DIM) + 1e-6f);

    float4 gg = *(const float4*)(g + lane * 4);
    vx.x *= rnorm * gg.x; vx.y *= rnorm * gg.y;
    vx.z *= rnorm * gg.z; vx.w *= rnorm * gg.w;

    float4 c  = *(const float4*)(cosb + (size_t)s * HEAD_DIM + lane * 4);
    float4 sn = *(const float4*)(sinb + (size_t)s * HEAD_DIM + lane * 4);
    float4 o;
    o.x = vx.x * c.x - vx.y * sn.x;
    o.y = vx.y * c.y + vx.x * sn.y;
    o.z = vx.z * c.z - vx.w * sn.z;
    o.w = vx.w * c.w + vx.z * sn.w;
    *(float4*)(ptr + lane * 4) = o;
}

// ===========================================================================
// Stage 3: flash attention on mma.sync tf32 (round-7 validated version).
// ===========================================================================
#define AT_THREADS 256
#define AT_QH 0
#define AT_QL (AT_QH + 64*132)
#define AT_KS (AT_QL + 64*132)
#define AT_VS (AT_KS + 64*132)
#define AT_PH (AT_VS + 64*136)
#define AT_PL (AT_PH + 64*68)
#define AT_RMAX (AT_PL + 64*68)
#define AT_RSUM (AT_RMAX + 128)
#define AT_TOTAL (AT_RSUM + 128)
#define AT_SMEM_BYTES (AT_TOTAL * 4)

__global__ __launch_bounds__(AT_THREADS, 1) void attn_mma_kernel(float* __restrict__ out)
{
    extern __shared__ uint32_t smu[];
    uint32_t* Qh = smu + AT_QH;
    uint32_t* Ql = smu + AT_QL;
    uint32_t* Ks = smu + AT_KS;
    uint32_t* Vs = smu + AT_VS;
    uint32_t* Ph = smu + AT_PH;
    uint32_t* Pl = smu + AT_PL;
    float* Rmax = (float*)(smu + AT_RMAX);
    float* Rsum = (float*)(smu + AT_RSUM);

    const int h    = blockIdx.y;
    const int q0   = blockIdx.x * 64;
    const int tid  = threadIdx.x;
    const int wid  = tid >> 5;
    const int lane = tid & 31;
    const int g    = lane >> 2;
    const int tg   = lane & 3;
    const int wm   = wid & 3;
    const int wh   = wid >> 2;
    const int ri0  = wm * 16 + g;
    const int ri1  = ri0 + 8;

    const float scale = 0.08838834764831845f;

    for (int i = tid; i < 64 * 32; i += AT_THREADS) {
        const int r  = i >> 5;
        const int c4 = (i & 31) * 4;
        float4 v = *(const float4*)(g_q + ((size_t)(q0 + r) * HEADS + h) * HEAD_DIM + c4);
        v.x *= scale; v.y *= scale; v.z *= scale; v.w *= scale;
        uint4 hh, ll;
        hh.x = tf32_rna(v.x); ll.x = tf32_rna(v.x - __uint_as_float(hh.x));
        hh.y = tf32_rna(v.y); ll.y = tf32_rna(v.y - __uint_as_float(hh.y));
        hh.z = tf32_rna(v.z); ll.z = tf32_rna(v.z - __uint_as_float(hh.z));
        hh.w = tf32_rna(v.w); ll.w = tf32_rna(v.w - __uint_as_float(hh.w));
        *(uint4*)(Qh + r * 132 + c4) = hh;
        *(uint4*)(Ql + r * 132 + c4) = ll;
    }

    float m0 = -INFINITY, m1 = -INFINITY, l0 = 0.f, l1 = 0.f;
    float o[8][4];
    #pragma unroll
    for (int j = 0; j < 8; j++)
        #pragma unroll
        for (int r = 0; r < 4; r++) o[j][r] = 0.f;

    for (int kv0 = 0; kv0 < S_LEN; kv0 += 64) {
        __syncthreads();
        for (int i = tid; i < 64 * 32; i += AT_THREADS) {
            const int r  = i >> 5;
            const int c4 = (i & 31) * 4;
            float4 kv4 = *(const float4*)(g_k + ((size_t)(kv0 + r) * HEADS + h) * HEAD_DIM + c4);
            uint4 t;
            t.x = tf32_rna(kv4.x); t.y = tf32_rna(kv4.y);
            t.z = tf32_rna(kv4.z); t.w = tf32_rna(kv4.w);
            *(uint4*)(Ks + r * 132 + c4) = t;
            float4 vv4 = *(const float4*)(g_v + ((size_t)(kv0 + r) * HEADS + h) * HEAD_DIM + c4);
            uint4 u;
            u.x = tf32_rna(vv4.x); u.y = tf32_rna(vv4.y);
            u.z = tf32_rna(vv4.z); u.w = tf32_rna(vv4.w);
            *(uint4*)(Vs + r * 136 + c4) = u;
        }
        __syncthreads();

        float s[4][4];
        #pragma unroll
        for (int j = 0; j < 4; j++)
            #pragma unroll
            for (int r = 0; r < 4; r++) s[j][r] = 0.f;

        #pragma unroll
        for (int kk8 = 0; kk8 < 16; kk8++) {
            const int kk = kk8 * 8;
            uint32_t ah[4], al[4];
            ah[0] = Qh[ri0 * 132 + kk + tg];
            ah[1] = Qh[ri1 * 132 + kk + tg];
            ah[2] = Qh[ri0 * 132 + kk + tg + 4];
            ah[3] = Qh[ri1 * 132 + kk + tg + 4];
            al[0] = Ql[ri0 * 132 + kk + tg];
            al[1] = Ql[ri1 * 132 + kk + tg];
            al[2] = Ql[ri0 * 132 + kk + tg + 4];
            al[3] = Ql[ri1 * 132 + kk + tg + 4];
            #pragma unroll
            for (int j = 0; j < 4; j++) {
                const int nv = wh * 32 + j * 8 + g;
                uint32_t bb[2];
                bb[0] = Ks[nv * 132 + kk + tg];
                bb[1] = Ks[nv * 132 + kk + tg + 4];
                mma_tf32(s[j], ah, bb);
                mma_tf32(s[j], al, bb);
            }
        }

        float mx0 = fmaxf(fmaxf(s[0][0], s[0][1]), fmaxf(s[1][0], s[1][1]));
        mx0 = fmaxf(mx0, fmaxf(fmaxf(s[2][0], s[2][1]), fmaxf(s[3][0], s[3][1])));
        float mx1 = fmaxf(fmaxf(s[0][2], s[0][3]), fmaxf(s[1][2], s[1][3]));
        mx1 = fmaxf(mx1, fmaxf(fmaxf(s[2][2], s[2][3]), fmaxf(s[3][2], s[3][3])));
        mx0 = fmaxf(mx0, __shfl_xor_sync(0xffffffffu, mx0, 1));
        mx0 = fmaxf(mx0, __shfl_xor_sync(0xffffffffu, mx0, 2));
        mx1 = fmaxf(mx1, __shfl_xor_sync(0xffffffffu, mx1, 1));
        mx1 = fmaxf(mx1, __shfl_xor_sync(0xffffffffu, mx1, 2));
        if (tg == 0) {
            Rmax[wh * 64 + ri0] = mx0;
            Rmax[wh * 64 + ri1] = mx1;
        }
        __syncthreads();
        const float mt0 = fmaxf(Rmax[ri0], Rmax[64 + ri0]);
        const float mt1 = fmaxf(Rmax[ri1], Rmax[64 + ri1]);
        const float mn0 = fmaxf(m0, mt0);
        const float mn1 = fmaxf(m1, mt1);
        const float alpha0 = __expf(m0 - mn0);
        const float alpha1 = __expf(m1 - mn1);

        float sum0 = 0.f, sum1 = 0.f;
        #pragma unroll
        for (int j = 0; j < 4; j++) {
            const int col = wh * 32 + j * 8 + 2 * tg;
            const float p0 = __expf(s[j][0] - mn0);
            const float p1 = __expf(s[j][1] - mn0);
            const float p2 = __expf(s[j][2] - mn1);
            const float p3 = __expf(s[j][3] - mn1);
            sum0 += p0 + p1;
            sum1 += p2 + p3;
            uint32_t hv, lv;
            hv = tf32_rna(p0); lv = tf32_rna(p0 - __uint_as_float(hv));
            Ph[ri0 * 68 + col] = hv; Pl[ri0 * 68 + col] = lv;
            hv = tf32_rna(p1); lv = tf32_rna(p1 - __uint_as_float(hv));
            Ph[ri0 * 68 + col + 1] = hv; Pl[ri0 * 68 + col + 1] = lv;
            hv = tf32_rna(p2); lv = tf32_rna(p2 - __uint_as_float(hv));
            Ph[ri1 * 68 + col] = hv; Pl[ri1 * 68 + col] = lv;
            hv = tf32_rna(p3); lv = tf32_rna(p3 - __uint_as_float(hv));
            Ph[ri1 * 68 + col + 1] = hv; Pl[ri1 * 68 + col + 1] = lv;
        }
        sum0 += __shfl_xor_sync(0xffffffffu, sum0, 1);
        sum0 += __shfl_xor_sync(0xffffffffu, sum0, 2);
        sum1 += __shfl_xor_sync(0xffffffffu, sum1, 1);
        sum1 += __shfl_xor_sync(0xffffffffu, sum1, 2);
        if (tg == 0) {
            Rsum[wh * 64 + ri0] = sum0;
            Rsum[wh * 64 + ri1] = sum1;
        }
        __syncthreads();
        l0 = l0 * alpha0 + Rsum[ri0] + Rsum[64 + ri0];
        l1 = l1 * alpha1 + Rsum[ri1] + Rsum[64 + ri1];
        m0 = mn0; m1 = mn1;

        #pragma unroll
        for (int j = 0; j < 8; j++) {
            o[j][0] *= alpha0; o[j][1] *= alpha0;
            o[j][2] *= alpha1; o[j][3] *= alpha1;
        }

        #pragma unroll
        for (int kk8 = 0; kk8 < 8; kk8++) {
            const int kk = kk8 * 8;
            uint32_t ah[4], al[4];
            ah[0] = Ph[ri0 * 68 + kk + tg];
            ah[1] = Ph[ri1 * 68 + kk + tg];
            ah[2] = Ph[ri0 * 68 + kk + tg + 4];
            ah[3] = Ph[ri1 * 68 + kk + tg + 4];
            al[0] = Pl[ri0 * 68 + kk + tg];
            al[1] = Pl[ri1 * 68 + kk + tg];
            al[2] = Pl[ri0 * 68 + kk + tg + 4];
            al[3] = Pl[ri1 * 68 + kk + tg + 4];
            #pragma unroll
            for (int j = 0; j < 8; j++) {
                const int nd = wh * 64 + j * 8 + g;
                uint32_t bb[2];
                bb[0] = Vs[(kk + tg)     * 136 + nd];
                bb[1] = Vs[(kk + tg + 4) * 136 + nd];
                mma_tf32(o[j], ah, bb);
                mma_tf32(o[j], al, bb);
            }
        }
    }

    const float inv0 = 1.f / l0;
    const float inv1 = 1.f / l1;
    #pragma unroll
    for (int j = 0; j < 8; j++) {
        const int d = h * HEAD_DIM + wh * 64 + j * 8 + 2 * tg;
        *(float2*)(out + (size_t)(q0 + ri0) * DIM + d) =
            make_float2(o[j][0] * inv0, o[j][1] * inv0);
        *(float2*)(out + (size_t)(q0 + ri1) * DIM + d) =
            make_float2(o[j][2] * inv1, o[j][3] * inv1);
    }
}

// ---------------------------------------------------------------------------
extern "C" void kernel_launch(void* const* d_in, const int* in_sizes, int n_in,
                              void* d_out, int out_size)
{
    (void)in_sizes; (void)n_in; (void)out_size;
    const float* x  = (const float*)d_in[0];
    const float* cs = (const float*)d_in[1];
    const float* sn = (const float*)d_in[2];
    const float* Wq = (const float*)d_in[3];
    const float* bq = (const float*)d_in[4];
    const float* Wk = (const float*)d_in[5];
    const float* bk = (const float*)d_in[6];
    const float* Wv = (const float*)d_in[7];
    const float* bv = (const float*)d_in[8];
    const float* gq = (const float*)d_in[9];
    const float* gk = (const float*)d_in[10];
    float* out = (float*)d_out;

    // Stage 1: QKV projections (mma.sync tf32, plain A/B, 2 CTAs/SM)
    cudaFuncSetAttribute(qkv_mma_kernel, cudaFuncAttributeMaxDynamicSharedMemorySize,
                         QSMEM_BYTES);
    dim3 gg(DIM / 128, S_LEN / 128, 3);
    qkv_mma_kernel<<<gg, 256, QSMEM_BYTES>>>(x, Wq, bq, Wk, bk, Wv, bv);

    // Stage 2: RMSNorm + RoPE on q, k
    const int warps  = 2 * S_LEN * HEADS;
    const int thr    = 256;
    const int blocks = (warps * 32 + thr - 1) / thr;
    rms_rope_kernel<<<blocks, thr>>>(cs, sn, gq, gk);

    // Stage 3: attention (mma.sync tf32)
    cudaFuncSetAttribute(attn_mma_kernel, cudaFuncAttributeMaxDynamicSharedMemorySize,
                         AT_SMEM_BYTES);
    dim3 ga(S_LEN / 64, HEADS);
    attn_mma_kernel<<<ga, AT_THREADS, AT_SMEM_BYTES>>>(out);
}

// round 9
// speedup vs baseline: 1.4939x; 1.4939x over previous
#include <cuda_runtime.h>
#include <math.h>
#include <stdint.h>

#define S_LEN    2048
#define DIM      3072
#define HEADS    24
#define HEAD_DIM 128

// Scratch (no cudaMalloc allowed): q, k, v post-projection
__device__ float g_q[S_LEN * DIM];
__device__ float g_k[S_LEN * DIM];
__device__ float g_v[S_LEN * DIM];

// ---- helpers -------------------------------------------------------------
__device__ __forceinline__ uint32_t tf32_rna(float x) {
    uint32_t r;
    asm("cvt.rna.tf32.f32 %0, %1;" : "=r"(r) : "f"(x));
    return r;
}
__device__ __forceinline__ void mma_tf32(float c[4], const uint32_t a[4], const uint32_t b[2]) {
    asm volatile(
        "mma.sync.aligned.m16n8k8.row.col.f32.tf32.tf32.f32 "
        "{%0,%1,%2,%3}, {%4,%5,%6,%7}, {%8,%9}, {%0,%1,%2,%3};"
        : "+f"(c[0]), "+f"(c[1]), "+f"(c[2]), "+f"(c[3])
        : "r"(a[0]), "r"(a[1]), "r"(a[2]), "r"(a[3]), "r"(b[0]), "r"(b[1]));
}
__device__ __forceinline__ void cp_async16(uint32_t smem_dst, const void* gsrc) {
    asm volatile("cp.async.cg.shared.global [%0], [%1], 16;"
                 :: "r"(smem_dst), "l"(gsrc));
}
__device__ __forceinline__ void cp_commit() {
    asm volatile("cp.async.commit_group;" ::: "memory");
}
template <int N>
__device__ __forceinline__ void cp_wait() {
    asm volatile("cp.async.wait_group %0;" :: "n"(N) : "memory");
}

// ===========================================================================
// Stage 1: QKV projection via mma.sync tf32.
// CTA tile 128x256, 8 warps (2m x 4n), warp tile 64x64 (4i x 8j of m16n8k8).
// K-chunk 32, 2-stage cp.async pipeline; raw fp32 in smem, rna-convert at
// fragment load. 125 B LDS per MMA (3x less than round 8).
// Strides: A 36 (banks 4g+tg bijective), B 264 (banks 8tg+g bijective).
// ===========================================================================
#define QA_STRIDE 36
#define QB_STRIDE 264
#define QA_FLOATS (128 * QA_STRIDE)              // 4608
#define QB_FLOATS (32 * QB_STRIDE)               // 8448
#define QBUF_FLOATS (QA_FLOATS + QB_FLOATS)      // 13056
#define QSMEM_BYTES (2 * QBUF_FLOATS * 4)        // 104448
#define NCHUNK (DIM / 32)                        // 96

__global__ __launch_bounds__(256, 1) void qkv_mma_kernel(
    const float* __restrict__ x,
    const float* __restrict__ Wq, const float* __restrict__ bq,
    const float* __restrict__ Wk, const float* __restrict__ bk,
    const float* __restrict__ Wv, const float* __restrict__ bv)
{
    extern __shared__ float smem[];
    const float* W; const float* bias; float* out;
    if (blockIdx.z == 0)      { W = Wq; bias = bq; out = g_q; }
    else if (blockIdx.z == 1) { W = Wk; bias = bk; out = g_k; }
    else                      { W = Wv; bias = bv; out = g_v; }

    const int tid  = threadIdx.x;
    const int wid  = tid >> 5;
    const int lane = tid & 31;
    const int g    = lane >> 2;
    const int tg   = lane & 3;
    const int wm   = wid >> 2;       // 0..1 -> rows 64*wm
    const int wn   = wid & 3;        // 0..3 -> cols 64*wn
    const int row0 = blockIdx.y * 128;
    const int col0 = blockIdx.x * 256;

    // fill indices: A 128x32 floats (4 x 16B/thread), B 32x256 (8 x 16B/thread)
    const int arow = tid >> 1;              // 0..127
    const int acol = (tid & 1) * 16;        // 0/16
    const int brow = tid >> 3;              // 0..31
    const int bcol = (tid & 7) * 32;        // 0..224

    const float* xA = x + (size_t)(row0 + arow) * DIM + acol;
    const float* wB = W + (size_t)brow * DIM + col0 + bcol;

    const uint32_t smem_u32 = (uint32_t)__cvta_generic_to_shared(smem);
    auto As = [&](int b) -> uint32_t { return smem_u32 + (uint32_t)(b * QBUF_FLOATS) * 4u; };
    auto Bs = [&](int b) -> uint32_t { return As(b) + QA_FLOATS * 4u; };

    auto issue_chunk = [&](int c, int b) {
        const float* asrc = xA + c * 32;
        const uint32_t adst = As(b) + (uint32_t)(arow * QA_STRIDE + acol) * 4u;
        #pragma unroll
        for (int j = 0; j < 4; j++)
            cp_async16(adst + j * 16u, asrc + j * 4);
        const float* bsrc = wB + (size_t)(c * 32) * DIM;
        const uint32_t bdst = Bs(b) + (uint32_t)(brow * QB_STRIDE + bcol) * 4u;
        #pragma unroll
        for (int j = 0; j < 8; j++)
            cp_async16(bdst + j * 16u, bsrc + j * 4);
        cp_commit();
    };

    float acc[4][8][4];
    #pragma unroll
    for (int i = 0; i < 4; i++)
        #pragma unroll
        for (int j = 0; j < 8; j++)
            #pragma unroll
            for (int r = 0; r < 4; r++) acc[i][j][r] = 0.f;

    issue_chunk(0, 0);

    for (int c = 0; c < NCHUNK; c++) {
        const int b = c & 1;
        const bool has_next = (c + 1) < NCHUNK;
        if (has_next) issue_chunk(c + 1, b ^ 1);
        if (has_next) cp_wait<1>(); else cp_wait<0>();
        __syncthreads();

        const float* Ap = smem + (size_t)b * QBUF_FLOATS;
        const float* Bp = smem + (size_t)b * QBUF_FLOATS + QA_FLOATS;

        #pragma unroll
        for (int kk8 = 0; kk8 < 4; kk8++) {
            const int kk = kk8 * 8;
            // B fragments for this warp's 8 n-tiles
            uint32_t bb[8][2];
            #pragma unroll
            for (int j = 0; j < 8; j++) {
                const int n = wn * 64 + j * 8 + g;
                bb[j][0] = tf32_rna(Bp[(kk + tg)     * QB_STRIDE + n]);
                bb[j][1] = tf32_rna(Bp[(kk + tg + 4) * QB_STRIDE + n]);
            }
            #pragma unroll
            for (int i = 0; i < 4; i++) {
                const int r = wm * 64 + i * 16 + g;
                uint32_t ah[4];
                ah[0] = tf32_rna(Ap[(r)     * QA_STRIDE + kk + tg]);
                ah[1] = tf32_rna(Ap[(r + 8) * QA_STRIDE + kk + tg]);
                ah[2] = tf32_rna(Ap[(r)     * QA_STRIDE + kk + tg + 4]);
                ah[3] = tf32_rna(Ap[(r + 8) * QA_STRIDE + kk + tg + 4]);
                #pragma unroll
                for (int j = 0; j < 8; j++)
                    mma_tf32(acc[i][j], ah, bb[j]);
            }
        }
        __syncthreads();   // all warps done reading buf b before it is refilled
    }

    // ---- epilogue: add bias, store ----
    #pragma unroll
    for (int j = 0; j < 8; j++) {
        const int n = col0 + wn * 64 + j * 8 + 2 * tg;
        const float2 bb = *(const float2*)(bias + n);
        #pragma unroll
        for (int i = 0; i < 4; i++) {
            const int r = row0 + wm * 64 + i * 16 + g;
            float2 o0 = make_float2(acc[i][j][0] + bb.x, acc[i][j][1] + bb.y);
            float2 o1 = make_float2(acc[i][j][2] + bb.x, acc[i][j][3] + bb.y);
            *(float2*)(out + (size_t)r * DIM + n)       = o0;
            *(float2*)(out + (size_t)(r + 8) * DIM + n) = o1;
        }
    }
}

// ---------------------------------------------------------------------------
// Stage 2: per-head RMSNorm + RoPE applied in place to g_q and g_k.
// ---------------------------------------------------------------------------
__global__ __launch_bounds__(256) void rms_rope_kernel(
    const float* __restrict__ cosb, const float* __restrict__ sinb,
    const float* __restrict__ gq, const float* __restrict__ gk)
{
    const int gw   = (blockIdx.x * blockDim.x + threadIdx.x) >> 5;
    const int lane = threadIdx.x & 31;
    const int rows = S_LEN * HEADS;
    if (gw >= 2 * rows) return;

    const int t  = (gw >= rows) ? 1 : 0;
    const int rr = t ? (gw - rows) : gw;
    const int s  = rr / HEADS;

    float* ptr = (t ? g_k : g_q) + (size_t)rr * HEAD_DIM;
    const float* g = t ? gk : gq;

    float4 vx = *(float4*)(ptr + lane * 4);
    float ss = vx.x * vx.x + vx.y * vx.y + vx.z * vx.z + vx.w * vx.w;
    #pragma unroll
    for (int o = 16; o > 0; o >>= 1) ss += __shfl_xor_sync(0xffffffffu, ss, o);
    const float rnorm = rsqrtf(ss * (1.0f / HEAD_DIM) + 1e-6f);

    float4 gg = *(const float4*)(g + lane * 4);
    vx.x *= rnorm * gg.x; vx.y *= rnorm * gg.y;
    vx.z *= rnorm * gg.z; vx.w *= rnorm * gg.w;

    float4 c  = *(const float4*)(cosb + (size_t)s * HEAD_DIM + lane * 4);
    float4 sn = *(const float4*)(sinb + (size_t)s * HEAD_DIM + lane * 4);
    float4 o;
    o.x = vx.x * c.x - vx.y * sn.x;
    o.y = vx.y * c.y + vx.x * sn.y;
    o.z = vx.z * c.z - vx.w * sn.z;
    o.w = vx.w * c.w + vx.z * sn.w;
    *(float4*)(ptr + lane * 4) = o;
}

// ===========================================================================
// Stage 3: flash attention on mma.sync tf32 (round-7 validated version).
// ===========================================================================
#define AT_THREADS 256
#define AT_QH 0
#define AT_QL (AT_QH + 64*132)
#define AT_KS (AT_QL + 64*132)
#define AT_VS (AT_KS + 64*132)
#define AT_PH (AT_VS + 64*136)
#define AT_PL (AT_PH + 64*68)
#define AT_RMAX (AT_PL + 64*68)
#define AT_RSUM (AT_RMAX + 128)
#define AT_TOTAL (AT_RSUM + 128)
#define AT_SMEM_BYTES (AT_TOTAL * 4)

__global__ __launch_bounds__(AT_THREADS, 1) void attn_mma_kernel(float* __restrict__ out)
{
    extern __shared__ uint32_t smu[];
    uint32_t* Qh = smu + AT_QH;
    uint32_t* Ql = smu + AT_QL;
    uint32_t* Ks = smu + AT_KS;
    uint32_t* Vs = smu + AT_VS;
    uint32_t* Ph = smu + AT_PH;
    uint32_t* Pl = smu + AT_PL;
    float* Rmax = (float*)(smu + AT_RMAX);
    float* Rsum = (float*)(smu + AT_RSUM);

    const int h    = blockIdx.y;
    const int q0   = blockIdx.x * 64;
    const int tid  = threadIdx.x;
    const int wid  = tid >> 5;
    const int lane = tid & 31;
    const int g    = lane >> 2;
    const int tg   = lane & 3;
    const int wm   = wid & 3;
    const int wh   = wid >> 2;
    const int ri0  = wm * 16 + g;
    const int ri1  = ri0 + 8;

    const float scale = 0.08838834764831845f;

    for (int i = tid; i < 64 * 32; i += AT_THREADS) {
        const int r  = i >> 5;
        const int c4 = (i & 31) * 4;
        float4 v = *(const float4*)(g_q + ((size_t)(q0 + r) * HEADS + h) * HEAD_DIM + c4);
        v.x *= scale; v.y *= scale; v.z *= scale; v.w *= scale;
        uint4 hh, ll;
        hh.x = tf32_rna(v.x); ll.x = tf32_rna(v.x - __uint_as_float(hh.x));
        hh.y = tf32_rna(v.y); ll.y = tf32_rna(v.y - __uint_as_float(hh.y));
        hh.z = tf32_rna(v.z); ll.z = tf32_rna(v.z - __uint_as_float(hh.z));
        hh.w = tf32_rna(v.w); ll.w = tf32_rna(v.w - __uint_as_float(hh.w));
        *(uint4*)(Qh + r * 132 + c4) = hh;
        *(uint4*)(Ql + r * 132 + c4) = ll;
    }

    float m0 = -INFINITY, m1 = -INFINITY, l0 = 0.f, l1 = 0.f;
    float o[8][4];
    #pragma unroll
    for (int j = 0; j < 8; j++)
        #pragma unroll
        for (int r = 0; r < 4; r++) o[j][r] = 0.f;

    for (int kv0 = 0; kv0 < S_LEN; kv0 += 64) {
        __syncthreads();
        for (int i = tid; i < 64 * 32; i += AT_THREADS) {
            const int r  = i >> 5;
            const int c4 = (i & 31) * 4;
            float4 kv4 = *(const float4*)(g_k + ((size_t)(kv0 + r) * HEADS + h) * HEAD_DIM + c4);
            uint4 t;
            t.x = tf32_rna(kv4.x); t.y = tf32_rna(kv4.y);
            t.z = tf32_rna(kv4.z); t.w = tf32_rna(kv4.w);
            *(uint4*)(Ks + r * 132 + c4) = t;
            float4 vv4 = *(const float4*)(g_v + ((size_t)(kv0 + r) * HEADS + h) * HEAD_DIM + c4);
            uint4 u;
            u.x = tf32_rna(vv4.x); u.y = tf32_rna(vv4.y);
            u.z = tf32_rna(vv4.z); u.w = tf32_rna(vv4.w);
            *(uint4*)(Vs + r * 136 + c4) = u;
        }
        __syncthreads();

        float s[4][4];
        #pragma unroll
        for (int j = 0; j < 4; j++)
            #pragma unroll
            for (int r = 0; r < 4; r++) s[j][r] = 0.f;

        #pragma unroll
        for (int kk8 = 0; kk8 < 16; kk8++) {
            const int kk = kk8 * 8;
            uint32_t ah[4], al[4];
            ah[0] = Qh[ri0 * 132 + kk + tg];
            ah[1] = Qh[ri1 * 132 + kk + tg];
            ah[2] = Qh[ri0 * 132 + kk + tg + 4];
            ah[3] = Qh[ri1 * 132 + kk + tg + 4];
            al[0] = Ql[ri0 * 132 + kk + tg];
            al[1] = Ql[ri1 * 132 + kk + tg];
            al[2] = Ql[ri0 * 132 + kk + tg + 4];
            al[3] = Ql[ri1 * 132 + kk + tg + 4];
            #pragma unroll
            for (int j = 0; j < 4; j++) {
                const int nv = wh * 32 + j * 8 + g;
                uint32_t bb[2];
                bb[0] = Ks[nv * 132 + kk + tg];
                bb[1] = Ks[nv * 132 + kk + tg + 4];
                mma_tf32(s[j], ah, bb);
                mma_tf32(s[j], al, bb);
            }
        }

        float mx0 = fmaxf(fmaxf(s[0][0], s[0][1]), fmaxf(s[1][0], s[1][1]));
        mx0 = fmaxf(mx0, fmaxf(fmaxf(s[2][0], s[2][1]), fmaxf(s[3][0], s[3][1])));
        float mx1 = fmaxf(fmaxf(s[0][2], s[0][3]), fmaxf(s[1][2], s[1][3]));
        mx1 = fmaxf(mx1, fmaxf(fmaxf(s[2][2], s[2][3]), fmaxf(s[3][2], s[3][3])));
        mx0 = fmaxf(mx0, __shfl_xor_sync(0xffffffffu, mx0, 1));
        mx0 = fmaxf(mx0, __shfl_xor_sync(0xffffffffu, mx0, 2));
        mx1 = fmaxf(mx1, __shfl_xor_sync(0xffffffffu, mx1, 1));
        mx1 = fmaxf(mx1, __shfl_xor_sync(0xffffffffu, mx1, 2));
        if (tg == 0) {
            Rmax[wh * 64 + ri0] = mx0;
            Rmax[wh * 64 + ri1] = mx1;
        }
        __syncthreads();
        const float mt0 = fmaxf(Rmax[ri0], Rmax[64 + ri0]);
        const float mt1 = fmaxf(Rmax[ri1], Rmax[64 + ri1]);
        const float mn0 = fmaxf(m0, mt0);
        const float mn1 = fmaxf(m1, mt1);
        const float alpha0 = __expf(m0 - mn0);
        const float alpha1 = __expf(m1 - mn1);

        float sum0 = 0.f, sum1 = 0.f;
        #pragma unroll
        for (int j = 0; j < 4; j++) {
            const int col = wh * 32 + j * 8 + 2 * tg;
            const float p0 = __expf(s[j][0] - mn0);
            const float p1 = __expf(s[j][1] - mn0);
            const float p2 = __expf(s[j][2] - mn1);
            const float p3 = __expf(s[j][3] - mn1);
            sum0 += p0 + p1;
            sum1 += p2 + p3;
            uint32_t hv, lv;
            hv = tf32_rna(p0); lv = tf32_rna(p0 - __uint_as_float(hv));
            Ph[ri0 * 68 + col] = hv; Pl[ri0 * 68 + col] = lv;
            hv = tf32_rna(p1); lv = tf32_rna(p1 - __uint_as_float(hv));
            Ph[ri0 * 68 + col + 1] = hv; Pl[ri0 * 68 + col + 1] = lv;
            hv = tf32_rna(p2); lv = tf32_rna(p2 - __uint_as_float(hv));
            Ph[ri1 * 68 + col] = hv; Pl[ri1 * 68 + col] = lv;
            hv = tf32_rna(p3); lv = tf32_rna(p3 - __uint_as_float(hv));
            Ph[ri1 * 68 + col + 1] = hv; Pl[ri1 * 68 + col + 1] = lv;
        }
        sum0 += __shfl_xor_sync(0xffffffffu, sum0, 1);
        sum0 += __shfl_xor_sync(0xffffffffu, sum0, 2);
        sum1 += __shfl_xor_sync(0xffffffffu, sum1, 1);
        sum1 += __shfl_xor_sync(0xffffffffu, sum1, 2);
        if (tg == 0) {
            Rsum[wh * 64 + ri0] = sum0;
            Rsum[wh * 64 + ri1] = sum1;
        }
        __syncthreads();
        l0 = l0 * alpha0 + Rsum[ri0] + Rsum[64 + ri0];
        l1 = l1 * alpha1 + Rsum[ri1] + Rsum[64 + ri1];
        m0 = mn0; m1 = mn1;

        #pragma unroll
        for (int j = 0; j < 8; j++) {
            o[j][0] *= alpha0; o[j][1] *= alpha0;
            o[j][2] *= alpha1; o[j][3] *= alpha1;
        }

        #pragma unroll
        for (int kk8 = 0; kk8 < 8; kk8++) {
            const int kk = kk8 * 8;
            uint32_t ah[4], al[4];
            ah[0] = Ph[ri0 * 68 + kk + tg];
            ah[1] = Ph[ri1 * 68 + kk + tg];
            ah[2] = Ph[ri0 * 68 + kk + tg + 4];
            ah[3] = Ph[ri1 * 68 + kk + tg + 4];
            al[0] = Pl[ri0 * 68 + kk + tg];
            al[1] = Pl[ri1 * 68 + kk + tg];
            al[2] = Pl[ri0 * 68 + kk + tg + 4];
            al[3] = Pl[ri1 * 68 + kk + tg + 4];
            #pragma unroll
            for (int j = 0; j < 8; j++) {
                const int nd = wh * 64 + j * 8 + g;
                uint32_t bb[2];
                bb[0] = Vs[(kk + tg)     * 136 + nd];
                bb[1] = Vs[(kk + tg + 4) * 136 + nd];
                mma_tf32(o[j], ah, bb);
                mma_tf32(o[j], al, bb);
            }
        }
    }

    const float inv0 = 1.f / l0;
    const float inv1 = 1.f / l1;
    #pragma unroll
    for (int j = 0; j < 8; j++) {
        const int d = h * HEAD_DIM + wh * 64 + j * 8 + 2 * tg;
        *(float2*)(out + (size_t)(q0 + ri0) * DIM + d) =
            make_float2(o[j][0] * inv0, o[j][1] * inv0);
        *(float2*)(out + (size_t)(q0 + ri1) * DIM + d) =
            make_float2(o[j][2] * inv1, o[j][3] * inv1);
    }
}

// ---------------------------------------------------------------------------
extern "C" void kernel_launch(void* const* d_in, const int* in_sizes, int n_in,
                              void* d_out, int out_size)
{
    (void)in_sizes; (void)n_in; (void)out_size;
    const float* x  = (const float*)d_in[0];
    const float* cs = (const float*)d_in[1];
    const float* sn = (const float*)d_in[2];
    const float* Wq = (const float*)d_in[3];
    const float* bq = (const float*)d_in[4];
    const float* Wk = (const float*)d_in[5];
    const float* bk = (const float*)d_in[6];
    const float* Wv = (const float*)d_in[7];
    const float* bv = (const float*)d_in[8];
    const float* gq = (const float*)d_in[9];
    const float* gk = (const float*)d_in[10];
    float* out = (float*)d_out;

    // Stage 1: QKV projections (mma.sync tf32, 64x64 warp tile, cp.async)
    cudaFuncSetAttribute(qkv_mma_kernel, cudaFuncAttributeMaxDynamicSharedMemorySize,
                         QSMEM_BYTES);
    dim3 gg(DIM / 256, S_LEN / 128, 3);
    qkv_mma_kernel<<<gg, 256, QSMEM_BYTES>>>(x, Wq, bq, Wk, bk, Wv, bv);

    // Stage 2: RMSNorm + RoPE on q, k
    const int warps  = 2 * S_LEN * HEADS;
    const int thr    = 256;
    const int blocks = (warps * 32 + thr - 1) / thr;
    rms_rope_kernel<<<blocks, thr>>>(cs, sn, gq, gk);

    // Stage 3: attention (mma.sync tf32)
    cudaFuncSetAttribute(attn_mma_kernel, cudaFuncAttributeMaxDynamicSharedMemorySize,
                         AT_SMEM_BYTES);
    dim3 ga(S_LEN / 64, HEADS);
    attn_mma_kernel<<<ga, AT_THREADS, AT_SMEM_BYTES>>>(out);
}

// round 10
// speedup vs baseline: 1.6796x; 1.1243x over previous
#include <cuda_runtime.h>
#include <math.h>
#include <stdint.h>

#define S_LEN    2048
#define DIM      3072
#define HEADS    24
#define HEAD_DIM 128

// Scratch (no cudaMalloc allowed): q, k, v post-projection
__device__ float g_q[S_LEN * DIM];
__device__ float g_k[S_LEN * DIM];
__device__ float g_v[S_LEN * DIM];

// ---- helpers -------------------------------------------------------------
__device__ __forceinline__ uint32_t tf32_rna(float x) {
    uint32_t r;
    asm("cvt.rna.tf32.f32 %0, %1;" : "=r"(r) : "f"(x));
    return r;
}
__device__ __forceinline__ void mma_tf32(float c[4], const uint32_t a[4], const uint32_t b[2]) {
    asm volatile(
        "mma.sync.aligned.m16n8k8.row.col.f32.tf32.tf32.f32 "
        "{%0,%1,%2,%3}, {%4,%5,%6,%7}, {%8,%9}, {%0,%1,%2,%3};"
        : "+f"(c[0]), "+f"(c[1]), "+f"(c[2]), "+f"(c[3])
        : "r"(a[0]), "r"(a[1]), "r"(a[2]), "r"(a[3]), "r"(b[0]), "r"(b[1]));
}
__device__ __forceinline__ void cp_async16(uint32_t smem_dst, const void* gsrc) {
    asm volatile("cp.async.cg.shared.global [%0], [%1], 16;"
                 :: "r"(smem_dst), "l"(gsrc));
}
__device__ __forceinline__ void cp_commit() {
    asm volatile("cp.async.commit_group;" ::: "memory");
}
template <int N>
__device__ __forceinline__ void cp_wait() {
    asm volatile("cp.async.wait_group %0;" :: "n"(N) : "memory");
}

// ===========================================================================
// Stage 1: QKV projection via mma.sync tf32.
// CTA tile 128x256, 8 warps (2m x 4n), warp tile 64x64 (4i x 8j of m16n8k8).
// K-chunk 32, 3-stage cp.async pipeline, ONE __syncthreads per chunk.
// Raw fp32 in smem, rna-convert at fragment load.
// Strides: A 36 (banks 4g+tg bijective), B 264 (banks 8tg+g bijective).
// ===========================================================================
#define QA_STRIDE 36
#define QB_STRIDE 264
#define QA_FLOATS (128 * QA_STRIDE)              // 4608
#define QB_FLOATS (32 * QB_STRIDE)               // 8448
#define QBUF_FLOATS (QA_FLOATS + QB_FLOATS)      // 13056
#define QSTAGES 3
#define QSMEM_BYTES (QSTAGES * QBUF_FLOATS * 4)  // 156672
#define NCHUNK (DIM / 32)                        // 96

__global__ __launch_bounds__(256, 1) void qkv_mma_kernel(
    const float* __restrict__ x,
    const float* __restrict__ Wq, const float* __restrict__ bq,
    const float* __restrict__ Wk, const float* __restrict__ bk,
    const float* __restrict__ Wv, const float* __restrict__ bv)
{
    extern __shared__ float smem[];
    const float* W; const float* bias; float* out;
    if (blockIdx.z == 0)      { W = Wq; bias = bq; out = g_q; }
    else if (blockIdx.z == 1) { W = Wk; bias = bk; out = g_k; }
    else                      { W = Wv; bias = bv; out = g_v; }

    const int tid  = threadIdx.x;
    const int wid  = tid >> 5;
    const int lane = tid & 31;
    const int g    = lane >> 2;
    const int tg   = lane & 3;
    const int wm   = wid >> 2;       // 0..1 -> rows 64*wm
    const int wn   = wid & 3;        // 0..3 -> cols 64*wn
    const int row0 = blockIdx.y * 128;
    const int col0 = blockIdx.x * 256;

    const int arow = tid >> 1;              // 0..127
    const int acol = (tid & 1) * 16;        // 0/16
    const int brow = tid >> 3;              // 0..31
    const int bcol = (tid & 7) * 32;        // 0..224

    const float* xA = x + (size_t)(row0 + arow) * DIM + acol;
    const float* wB = W + (size_t)brow * DIM + col0 + bcol;

    const uint32_t smem_u32 = (uint32_t)__cvta_generic_to_shared(smem);
    auto As = [&](int b) -> uint32_t { return smem_u32 + (uint32_t)(b * QBUF_FLOATS) * 4u; };
    auto Bs = [&](int b) -> uint32_t { return As(b) + QA_FLOATS * 4u; };

    auto issue_chunk = [&](int c, int b) {
        const float* asrc = xA + c * 32;
        const uint32_t adst = As(b) + (uint32_t)(arow * QA_STRIDE + acol) * 4u;
        #pragma unroll
        for (int j = 0; j < 4; j++)
            cp_async16(adst + j * 16u, asrc + j * 4);
        const float* bsrc = wB + (size_t)(c * 32) * DIM;
        const uint32_t bdst = Bs(b) + (uint32_t)(brow * QB_STRIDE + bcol) * 4u;
        #pragma unroll
        for (int j = 0; j < 8; j++)
            cp_async16(bdst + j * 16u, bsrc + j * 4);
    };

    float acc[4][8][4];
    #pragma unroll
    for (int i = 0; i < 4; i++)
        #pragma unroll
        for (int j = 0; j < 8; j++)
            #pragma unroll
            for (int r = 0; r < 4; r++) acc[i][j][r] = 0.f;

    issue_chunk(0, 0); cp_commit();
    issue_chunk(1, 1); cp_commit();

    for (int c = 0; c < NCHUNK; c++) {
        const int b = c % QSTAGES;
        cp_wait<1>();          // groups pending: {c, c+1} -> chunk c complete
        __syncthreads();       // also: all warps finished reading buffer of c-1
        if (c + 2 < NCHUNK) issue_chunk(c + 2, (c + 2) % QSTAGES);
        cp_commit();           // always commit (possibly empty) to keep counts exact

        const float* Ap = smem + (size_t)b * QBUF_FLOATS;
        const float* Bp = smem + (size_t)b * QBUF_FLOATS + QA_FLOATS;

        #pragma unroll
        for (int kk8 = 0; kk8 < 4; kk8++) {
            const int kk = kk8 * 8;
            uint32_t bb[8][2];
            #pragma unroll
            for (int j = 0; j < 8; j++) {
                const int n = wn * 64 + j * 8 + g;
                bb[j][0] = tf32_rna(Bp[(kk + tg)     * QB_STRIDE + n]);
                bb[j][1] = tf32_rna(Bp[(kk + tg + 4) * QB_STRIDE + n]);
            }
            #pragma unroll
            for (int i = 0; i < 4; i++) {
                const int r = wm * 64 + i * 16 + g;
                uint32_t ah[4];
                ah[0] = tf32_rna(Ap[(r)     * QA_STRIDE + kk + tg]);
                ah[1] = tf32_rna(Ap[(r + 8) * QA_STRIDE + kk + tg]);
                ah[2] = tf32_rna(Ap[(r)     * QA_STRIDE + kk + tg + 4]);
                ah[3] = tf32_rna(Ap[(r + 8) * QA_STRIDE + kk + tg + 4]);
                #pragma unroll
                for (int j = 0; j < 8; j++)
                    mma_tf32(acc[i][j], ah, bb[j]);
            }
        }
    }

    // ---- epilogue: add bias, store ----
    #pragma unroll
    for (int j = 0; j < 8; j++) {
        const int n = col0 + wn * 64 + j * 8 + 2 * tg;
        const float2 bb = *(const float2*)(bias + n);
        #pragma unroll
        for (int i = 0; i < 4; i++) {
            const int r = row0 + wm * 64 + i * 16 + g;
            float2 o0 = make_float2(acc[i][j][0] + bb.x, acc[i][j][1] + bb.y);
            float2 o1 = make_float2(acc[i][j][2] + bb.x, acc[i][j][3] + bb.y);
            *(float2*)(out + (size_t)r * DIM + n)       = o0;
            *(float2*)(out + (size_t)(r + 8) * DIM + n) = o1;
        }
    }
}

// ---------------------------------------------------------------------------
// Stage 2: per-head RMSNorm + RoPE applied in place to g_q and g_k.
// ---------------------------------------------------------------------------
__global__ __launch_bounds__(256) void rms_rope_kernel(
    const float* __restrict__ cosb, const float* __restrict__ sinb,
    const float* __restrict__ gq, const float* __restrict__ gk)
{
    const int gw   = (blockIdx.x * blockDim.x + threadIdx.x) >> 5;
    const int lane = threadIdx.x & 31;
    const int rows = S_LEN * HEADS;
    if (gw >= 2 * rows) return;

    const int t  = (gw >= rows) ? 1 : 0;
    const int rr = t ? (gw - rows) : gw;
    const int s  = rr / HEADS;

    float* ptr = (t ? g_k : g_q) + (size_t)rr * HEAD_DIM;
    const float* g = t ? gk : gq;

    float4 vx = *(float4*)(ptr + lane * 4);
    float ss = vx.x * vx.x + vx.y * vx.y + vx.z * vx.z + vx.w * vx.w;
    #pragma unroll
    for (int o = 16; o > 0; o >>= 1) ss += __shfl_xor_sync(0xffffffffu, ss, o);
    const float rnorm = rsqrtf(ss * (1.0f / HEAD_DIM) + 1e-6f);

    float4 gg = *(const float4*)(g + lane * 4);
    vx.x *= rnorm * gg.x; vx.y *= rnorm * gg.y;
    vx.z *= rnorm * gg.z; vx.w *= rnorm * gg.w;

    float4 c  = *(const float4*)(cosb + (size_t)s * HEAD_DIM + lane * 4);
    float4 sn = *(const float4*)(sinb + (size_t)s * HEAD_DIM + lane * 4);
    float4 o;
    o.x = vx.x * c.x - vx.y * sn.x;
    o.y = vx.y * c.y + vx.x * sn.y;
    o.z = vx.z * c.z - vx.w * sn.z;
    o.w = vx.w * c.w + vx.z * sn.w;
    *(float4*)(ptr + lane * 4) = o;
}

// ===========================================================================
// Stage 3: flash attention on mma.sync tf32, single-pass tf32 (no lo terms).
// CTA: 64 q-rows x 1 head, 8 warps = (wm 0-3 rowblock16, wh 0-1 col-half).
// Error: two-side tf32 rounding in S and PV (calibrated ~3.9e-4 contribution).
// Strides: Q 132 (A, ≡4 mod 32), K 132 (B via column, ≡4), V 136 (B, ≡8),
// P 68 (A, ≡4). All conflict-free.
// ===========================================================================
#define AT_THREADS 256
#define AT_QH 0
#define AT_KS (AT_QH + 64*132)
#define AT_VS (AT_KS + 64*132)
#define AT_PH (AT_VS + 64*136)
#define AT_RMAX (AT_PH + 64*68)
#define AT_RSUM (AT_RMAX + 128)
#define AT_TOTAL (AT_RSUM + 128)
#define AT_SMEM_BYTES (AT_TOTAL * 4)

__global__ __launch_bounds__(AT_THREADS, 1) void attn_mma_kernel(float* __restrict__ out)
{
    extern __shared__ uint32_t smu[];
    uint32_t* Qh = smu + AT_QH;
    uint32_t* Ks = smu + AT_KS;
    uint32_t* Vs = smu + AT_VS;
    uint32_t* Ph = smu + AT_PH;
    float* Rmax = (float*)(smu + AT_RMAX);
    float* Rsum = (float*)(smu + AT_RSUM);

    const int h    = blockIdx.y;
    const int q0   = blockIdx.x * 64;
    const int tid  = threadIdx.x;
    const int wid  = tid >> 5;
    const int lane = tid & 31;
    const int g    = lane >> 2;
    const int tg   = lane & 3;
    const int wm   = wid & 3;
    const int wh   = wid >> 2;
    const int ri0  = wm * 16 + g;
    const int ri1  = ri0 + 8;

    const float scale = 0.08838834764831845f;

    for (int i = tid; i < 64 * 32; i += AT_THREADS) {
        const int r  = i >> 5;
        const int c4 = (i & 31) * 4;
        float4 v = *(const float4*)(g_q + ((size_t)(q0 + r) * HEADS + h) * HEAD_DIM + c4);
        uint4 hh;
        hh.x = tf32_rna(v.x * scale);
        hh.y = tf32_rna(v.y * scale);
        hh.z = tf32_rna(v.z * scale);
        hh.w = tf32_rna(v.w * scale);
        *(uint4*)(Qh + r * 132 + c4) = hh;
    }

    float m0 = -INFINITY, m1 = -INFINITY, l0 = 0.f, l1 = 0.f;
    float o[8][4];
    #pragma unroll
    for (int j = 0; j < 8; j++)
        #pragma unroll
        for (int r = 0; r < 4; r++) o[j][r] = 0.f;

    for (int kv0 = 0; kv0 < S_LEN; kv0 += 64) {
        __syncthreads();
        for (int i = tid; i < 64 * 32; i += AT_THREADS) {
            const int r  = i >> 5;
            const int c4 = (i & 31) * 4;
            float4 kv4 = *(const float4*)(g_k + ((size_t)(kv0 + r) * HEADS + h) * HEAD_DIM + c4);
            uint4 t;
            t.x = tf32_rna(kv4.x); t.y = tf32_rna(kv4.y);
            t.z = tf32_rna(kv4.z); t.w = tf32_rna(kv4.w);
            *(uint4*)(Ks + r * 132 + c4) = t;
            float4 vv4 = *(const float4*)(g_v + ((size_t)(kv0 + r) * HEADS + h) * HEAD_DIM + c4);
            uint4 u;
            u.x = tf32_rna(vv4.x); u.y = tf32_rna(vv4.y);
            u.z = tf32_rna(vv4.z); u.w = tf32_rna(vv4.w);
            *(uint4*)(Vs + r * 136 + c4) = u;
        }
        __syncthreads();

        // ---- S = Q K^T ----
        float s[4][4];
        #pragma unroll
        for (int j = 0; j < 4; j++)
            #pragma unroll
            for (int r = 0; r < 4; r++) s[j][r] = 0.f;

        #pragma unroll
        for (int kk8 = 0; kk8 < 16; kk8++) {
            const int kk = kk8 * 8;
            uint32_t ah[4];
            ah[0] = Qh[ri0 * 132 + kk + tg];
            ah[1] = Qh[ri1 * 132 + kk + tg];
            ah[2] = Qh[ri0 * 132 + kk + tg + 4];
            ah[3] = Qh[ri1 * 132 + kk + tg + 4];
            #pragma unroll
            for (int j = 0; j < 4; j++) {
                const int nv = wh * 32 + j * 8 + g;
                uint32_t bb[2];
                bb[0] = Ks[nv * 132 + kk + tg];
                bb[1] = Ks[nv * 132 + kk + tg + 4];
                mma_tf32(s[j], ah, bb);
            }
        }

        // ---- row max ----
        float mx0 = fmaxf(fmaxf(s[0][0], s[0][1]), fmaxf(s[1][0], s[1][1]));
        mx0 = fmaxf(mx0, fmaxf(fmaxf(s[2][0], s[2][1]), fmaxf(s[3][0], s[3][1])));
        float mx1 = fmaxf(fmaxf(s[0][2], s[0][3]), fmaxf(s[1][2], s[1][3]));
        mx1 = fmaxf(mx1, fmaxf(fmaxf(s[2][2], s[2][3]), fmaxf(s[3][2], s[3][3])));
        mx0 = fmaxf(mx0, __shfl_xor_sync(0xffffffffu, mx0, 1));
        mx0 = fmaxf(mx0, __shfl_xor_sync(0xffffffffu, mx0, 2));
        mx1 = fmaxf(mx1, __shfl_xor_sync(0xffffffffu, mx1, 1));
        mx1 = fmaxf(mx1, __shfl_xor_sync(0xffffffffu, mx1, 2));
        if (tg == 0) {
            Rmax[wh * 64 + ri0] = mx0;
            Rmax[wh * 64 + ri1] = mx1;
        }
        __syncthreads();
        const float mn0 = fmaxf(m0, fmaxf(Rmax[ri0], Rmax[64 + ri0]));
        const float mn1 = fmaxf(m1, fmaxf(Rmax[ri1], Rmax[64 + ri1]));
        const float alpha0 = __expf(m0 - mn0);
        const float alpha1 = __expf(m1 - mn1);

        // ---- p = exp(s - m), stage tf32 P, partial row sums ----
        float sum0 = 0.f, sum1 = 0.f;
        #pragma unroll
        for (int j = 0; j < 4; j++) {
            const int col = wh * 32 + j * 8 + 2 * tg;
            const float p0 = __expf(s[j][0] - mn0);
            const float p1 = __expf(s[j][1] - mn0);
            const float p2 = __expf(s[j][2] - mn1);
            const float p3 = __expf(s[j][3] - mn1);
            sum0 += p0 + p1;
            sum1 += p2 + p3;
            Ph[ri0 * 68 + col]     = tf32_rna(p0);
            Ph[ri0 * 68 + col + 1] = tf32_rna(p1);
            Ph[ri1 * 68 + col]     = tf32_rna(p2);
            Ph[ri1 * 68 + col + 1] = tf32_rna(p3);
        }
        sum0 += __shfl_xor_sync(0xffffffffu, sum0, 1);
        sum0 += __shfl_xor_sync(0xffffffffu, sum0, 2);
        sum1 += __shfl_xor_sync(0xffffffffu, sum1, 1);
        sum1 += __shfl_xor_sync(0xffffffffu, sum1, 2);
        if (tg == 0) {
            Rsum[wh * 64 + ri0] = sum0;
            Rsum[wh * 64 + ri1] = sum1;
        }
        __syncthreads();
        l0 = l0 * alpha0 + Rsum[ri0] + Rsum[64 + ri0];
        l1 = l1 * alpha1 + Rsum[ri1] + Rsum[64 + ri1];
        m0 = mn0; m1 = mn1;

        #pragma unroll
        for (int j = 0; j < 8; j++) {
            o[j][0] *= alpha0; o[j][1] *= alpha0;
            o[j][2] *= alpha1; o[j][3] *= alpha1;
        }

        // ---- O += P V ----
        #pragma unroll
        for (int kk8 = 0; kk8 < 8; kk8++) {
            const int kk = kk8 * 8;
            uint32_t ah[4];
            ah[0] = Ph[ri0 * 68 + kk + tg];
            ah[1] = Ph[ri1 * 68 + kk + tg];
            ah[2] = Ph[ri0 * 68 + kk + tg + 4];
            ah[3] = Ph[ri1 * 68 + kk + tg + 4];
            #pragma unroll
            for (int j = 0; j < 8; j++) {
                const int nd = wh * 64 + j * 8 + g;
                uint32_t bb[2];
                bb[0] = Vs[(kk + tg)     * 136 + nd];
                bb[1] = Vs[(kk + tg + 4) * 136 + nd];
                mma_tf32(o[j], ah, bb);
            }
        }
    }

    const float inv0 = 1.f / l0;
    const float inv1 = 1.f / l1;
    #pragma unroll
    for (int j = 0; j < 8; j++) {
        const int d = h * HEAD_DIM + wh * 64 + j * 8 + 2 * tg;
        *(float2*)(out + (size_t)(q0 + ri0) * DIM + d) =
            make_float2(o[j][0] * inv0, o[j][1] * inv0);
        *(float2*)(out + (size_t)(q0 + ri1) * DIM + d) =
            make_float2(o[j][2] * inv1, o[j][3] * inv1);
    }
}

// ---------------------------------------------------------------------------
extern "C" void kernel_launch(void* const* d_in, const int* in_sizes, int n_in,
                              void* d_out, int out_size)
{
    (void)in_sizes; (void)n_in; (void)out_size;
    const float* x  = (const float*)d_in[0];
    const float* cs = (const float*)d_in[1];
    const float* sn = (const float*)d_in[2];
    const float* Wq = (const float*)d_in[3];
    const float* bq = (const float*)d_in[4];
    const float* Wk = (const float*)d_in[5];
    const float* bk = (const float*)d_in[6];
    const float* Wv = (const float*)d_in[7];
    const float* bv = (const float*)d_in[8];
    const float* gq = (const float*)d_in[9];
    const float* gk = (const float*)d_in[10];
    float* out = (float*)d_out;

    // Stage 1: QKV projections (mma.sync tf32, 3-stage cp.async pipeline)
    cudaFuncSetAttribute(qkv_mma_kernel, cudaFuncAttributeMaxDynamicSharedMemorySize,
                         QSMEM_BYTES);
    dim3 gg(DIM / 256, S_LEN / 128, 3);
    qkv_mma_kernel<<<gg, 256, QSMEM_BYTES>>>(x, Wq, bq, Wk, bk, Wv, bv);

    // Stage 2: RMSNorm + RoPE on q, k
    const int warps  = 2 * S_LEN * HEADS;
    const int thr    = 256;
    const int blocks = (warps * 32 + thr - 1) / thr;
    rms_rope_kernel<<<blocks, thr>>>(cs, sn, gq, gk);

    // Stage 3: attention (mma.sync tf32, single-pass)
    cudaFuncSetAttribute(attn_mma_kernel, cudaFuncAttributeMaxDynamicSharedMemorySize,
                         AT_SMEM_BYTES);
    dim3 ga(S_LEN / 64, HEADS);
    attn_mma_kernel<<<ga, AT_THREADS, AT_SMEM_BYTES>>>(out);
}